// round 15
// baseline (speedup 1.0000x reference)
#include <cuda_runtime.h>
#include <cuda_bf16.h>

typedef unsigned long long u64;
#define NSTATF 262144.0f   // 16*128*128 per-channel count
#define NTOT   33554432

// ---------------- device scratch ----------------
__device__ __align__(256) float g_y1 [NTOT];
__device__ __align__(256) float g_ysc[NTOT];
__device__ __align__(256) float g_y2 [NTOT];
__device__ __align__(256) float g_w1t [147456];  // [ci][tap][co]
__device__ __align__(256) float g_wsct[16384];   // [ci][co]
__device__ __align__(256) float g_w2t [16384];   // [ci][co]
__device__ float g_dcepart[16384];               // [8][16][128]
__device__ float g_dce[2048], g_spatial[2048], g_mod[2048];
__device__ float g_s1[128], g_q1[128], g_ssc[128], g_qsc[128], g_s2[128], g_q2[128];
__device__ float g_a1[128], g_b1[128], g_asc[128], g_bsc[128], g_a2[128], g_b2[128];

// ---------------- helpers ----------------
__device__ __forceinline__ u64 pack2(float lo, float hi){
    u64 r; asm("mov.b64 %0, {%1, %2};" : "=l"(r) : "f"(lo), "f"(hi)); return r;
}
__device__ __forceinline__ void unpack2(u64 v, float& lo, float& hi){
    asm("mov.b64 {%0, %1}, %2;" : "=f"(lo), "=f"(hi) : "l"(v));
}
__device__ __forceinline__ u64 ffma2(u64 a, u64 b, u64 c){
    u64 d; asm("fma.rn.f32x2 %0, %1, %2, %3;" : "=l"(d) : "l"(a), "l"(b), "l"(c)); return d;
}
__device__ __forceinline__ void cp16(void* dst, const void* src){
    unsigned sa = (unsigned)__cvta_generic_to_shared(dst);
    asm volatile("cp.async.cg.shared.global [%0], [%1], 16;" :: "r"(sa), "l"(src) : "memory");
}
__device__ __forceinline__ void cp_commit(){ asm volatile("cp.async.commit_group;" ::: "memory"); }
__device__ __forceinline__ void cp_wait1(){ asm volatile("cp.async.wait_group 1;" ::: "memory"); }
__device__ __forceinline__ void cp_wait0(){ asm volatile("cp.async.wait_group 0;" ::: "memory"); }
__device__ __forceinline__ float geluf(float v){ return 0.5f*v*(1.f + erff(v*0.70710678f)); }
__device__ __forceinline__ float siluf(float v){ return v / (1.f + __expf(-v)); }

// stats reduce: 8 channel partial sums across 16 consecutive lanes, then atomics
__device__ __forceinline__ void stat_reduce(float* ps, float* pq, int wg, int cg,
                                            float* S, float* Q){
    #pragma unroll
    for (int o = 8; o; o >>= 1){
        #pragma unroll
        for (int k = 0; k < 8; k++){
            ps[k] += __shfl_xor_sync(0xffffffffu, ps[k], o, 16);
            pq[k] += __shfl_xor_sync(0xffffffffu, pq[k], o, 16);
        }
    }
    if (wg == 0){
        #pragma unroll
        for (int k = 0; k < 8; k++){
            atomicAdd(&S[cg*8+k], ps[k]);
            atomicAdd(&Q[cg*8+k], pq[k]);
        }
    }
}

// ---------------- K_init: weight transposes + zero stats ----------------
__global__ void k_init(const float* __restrict__ c1w, const float* __restrict__ c2w,
                       const float* __restrict__ scw){
    int i = blockIdx.x * blockDim.x + threadIdx.x;
    int n = blockDim.x * gridDim.x;
    for (int d = i; d < 147456; d += n){
        int co = d & 127, tap = (d >> 7) % 9, ci = d / 1152;
        g_w1t[d] = c1w[(co*128 + ci)*9 + tap];
    }
    for (int d = i; d < 16384; d += n){
        int co = d & 127, ci = d >> 7;
        g_w2t[d]  = c2w[co*128 + ci];
        g_wsct[d] = scw[co*128 + ci];
    }
    if (i < 128){ g_s1[i]=0.f; g_q1[i]=0.f; g_ssc[i]=0.f; g_qsc[i]=0.f; g_s2[i]=0.f; g_q2[i]=0.f; }
}

// ---------------- DCE FFN ----------------
__global__ __launch_bounds__(128) void k_dce1(const float* __restrict__ dce,
                                              const float* __restrict__ W1){
    int kb = blockIdx.x, b = blockIdx.y, c = threadIdx.x;
    __shared__ float sd[1600];
    const float* src = dce + b*12800 + kb*1600;
    for (int i = c; i < 1600; i += 128) sd[i] = src[i];
    __syncthreads();
    const float* wp = W1 + (size_t)kb*1600*128 + c;
    float acc = 0.f;
    #pragma unroll 8
    for (int k = 0; k < 1600; k++) acc = fmaf(sd[k], wp[(size_t)k*128], acc);
    g_dcepart[(kb*16 + b)*128 + c] = acc;
}

__global__ __launch_bounds__(128) void k_dce2(const float* __restrict__ b1,
                                              const float* __restrict__ W2,
                                              const float* __restrict__ b2){
    int b = blockIdx.x, c = threadIdx.x;
    __shared__ float sh[128];
    float acc = b1[c];
    #pragma unroll
    for (int kb = 0; kb < 8; kb++) acc += g_dcepart[(kb*16 + b)*128 + c];
    sh[c] = geluf(acc);
    __syncthreads();
    float f = b2[c];
    #pragma unroll 4
    for (int k = 0; k < 128; k++) f = fmaf(sh[k], W2[k*128 + c], f);
    g_dce[b*128 + c] = f;
}

// ---------------- spatial mean of padded depthwise 3x3 via rectangle sums ----------------
__global__ __launch_bounds__(256) void k_spatial(const float* __restrict__ x,
                                                 const float* __restrict__ dw){
    int c = blockIdx.x, b = blockIdx.y, tid = threadIdx.x;
    const float* base = x + (size_t)(b*128 + c) * 16384;
    const float4* xf = (const float4*)base;
    float tot=0.f, r0=0.f, rl=0.f, c0=0.f, cl=0.f;
    for (int i = tid; i < 4096; i += 256){
        float4 v = xf[i];
        float s = v.x + v.y + v.z + v.w;
        int row = i >> 5;
        tot += s;
        if (row == 0)       r0 += s;
        if (row == 127)     rl += s;
        if ((i & 31) == 0)  c0 += v.x;
        if ((i & 31) == 31) cl += v.w;
    }
    __shared__ float red[5][256];
    red[0][tid]=tot; red[1][tid]=r0; red[2][tid]=rl; red[3][tid]=c0; red[4][tid]=cl;
    __syncthreads();
    for (int s = 128; s > 0; s >>= 1){
        if (tid < s){
            #pragma unroll
            for (int a = 0; a < 5; a++) red[a][tid] += red[a][tid + s];
        }
        __syncthreads();
    }
    if (tid == 0){
        float T=red[0][0], R0=red[1][0], RL=red[2][0], C0=red[3][0], CL=red[4][0];
        float x00 = base[0], x0w = base[127], xh0 = base[127*128], xhw = base[127*128+127];
        float sp = 0.f;
        #pragma unroll
        for (int ky = 0; ky < 3; ky++){
            #pragma unroll
            for (int kx = 0; kx < 3; kx++){
                float rE = (ky==0) ? RL : (ky==2) ? R0 : 0.f;
                float cE = (kx==0) ? CL : (kx==2) ? C0 : 0.f;
                float crn = 0.f;
                if (ky==0 && kx==0) crn = xhw;
                else if (ky==0 && kx==2) crn = xh0;
                else if (ky==2 && kx==0) crn = x0w;
                else if (ky==2 && kx==2) crn = x00;
                sp += dw[c*9 + ky*3 + kx] * (T - rE - cE + crn);
            }
        }
        g_spatial[b*128 + c] = sp * (1.f/16384.f);
    }
}

// ---------------- SE modulation ----------------
__global__ __launch_bounds__(128) void k_mod(const float* __restrict__ Wsh, const float* __restrict__ bsh,
                                             const float* __restrict__ Wex, const float* __restrict__ bex){
    int b = blockIdx.x, c = threadIdx.x;
    __shared__ float sm[128], ss[64];
    sm[c] = g_dce[b*128 + c] * g_spatial[b*128 + c];
    __syncthreads();
    if (c < 64){
        float t = bsh[c];
        #pragma unroll 4
        for (int k = 0; k < 128; k++) t = fmaf(sm[k], Wsh[k*64 + c], t);
        ss[c] = geluf(t);
    }
    __syncthreads();
    float u = bex[c];
    #pragma unroll 4
    for (int j = 0; j < 64; j++) u = fmaf(ss[j], Wex[j*128 + c], u);
    g_mod[b*128 + c] = 1.f / (1.f + __expf(-u));
}

// ---------------- conv3x3 (the heavy kernel): y1 = conv3x3(x*mod), + stats ----------------
__global__ __launch_bounds__(256, 2) void k_conv3(const float* __restrict__ x){
    int h = blockIdx.x, b = blockIdx.y, tid = threadIdx.x;
    int wg = tid & 15, cg = tid >> 4;         // 16 w-groups x 16 co-groups
    __shared__ __align__(16) float sW[2][9][128];
    __shared__ __align__(16) float sX[2][3][128];
    __shared__ float sMod[128];
    if (tid < 128) sMod[tid] = g_mod[b*128 + tid];
    bool v0 = (h > 0), v2 = (h < 127);
    const float* xb = x + (size_t)(b*128) * 16384;

    auto prefetch = [&](int ci, int buf){
        const float* wsrc = g_w1t + (size_t)ci * 1152;
        cp16(&sW[buf][0][0] + tid*4, wsrc + tid*4);
        if (tid < 32) cp16(&sW[buf][0][0] + (tid+256)*4, wsrc + (tid+256)*4);
        if (tid < 96){
            int r = tid >> 5, ch = tid & 31;
            int row = h - 1 + r;
            if (row >= 0 && row < 128)
                cp16(&sX[buf][r][ch*4], xb + (size_t)ci*16384 + row*128 + ch*4);
        }
        cp_commit();
    };

    u64 acc[4][8];
    #pragma unroll
    for (int p = 0; p < 4; p++)
        #pragma unroll
        for (int w = 0; w < 8; w++) acc[p][w] = 0ull;

    prefetch(0, 0);
    for (int ci = 0; ci < 128; ci++){
        int buf = ci & 1;
        __syncthreads();                       // prior iter done reading buf^1
        if (ci < 127){ prefetch(ci+1, buf^1); cp_wait1(); }
        else          { cp_wait0(); }
        __syncthreads();                       // this iter's data visible

        float s = sMod[ci];
        #pragma unroll
        for (int ky = 0; ky < 3; ky++){
            bool valid = (ky==0) ? v0 : ((ky==2) ? v2 : true);
            u64 xd[10];
            #pragma unroll
            for (int j = 0; j < 10; j++){
                int idx = wg*8 - 1 + j;
                float v = 0.f;
                if (valid && idx >= 0 && idx < 128) v = sX[buf][ky][idx] * s;
                xd[j] = pack2(v, v);
            }
            #pragma unroll
            for (int kx = 0; kx < 3; kx++){
                const float* wrow = &sW[buf][ky*3+kx][cg*8];
                u64 w0 = *(const u64*)(wrow+0);
                u64 w1 = *(const u64*)(wrow+2);
                u64 w2 = *(const u64*)(wrow+4);
                u64 w3 = *(const u64*)(wrow+6);
                #pragma unroll
                for (int w = 0; w < 8; w++){
                    acc[0][w] = ffma2(w0, xd[w+kx], acc[0][w]);
                    acc[1][w] = ffma2(w1, xd[w+kx], acc[1][w]);
                    acc[2][w] = ffma2(w2, xd[w+kx], acc[2][w]);
                    acc[3][w] = ffma2(w3, xd[w+kx], acc[3][w]);
                }
            }
        }
    }

    // stats + store
    float ps[8] = {0,0,0,0,0,0,0,0}, pq[8] = {0,0,0,0,0,0,0,0};
    #pragma unroll
    for (int p = 0; p < 4; p++){
        float lo, hi;
        float4 vlo0, vlo1, vhi0, vhi1;
        float flo[8], fhi[8];
        #pragma unroll
        for (int w = 0; w < 8; w++){
            unpack2(acc[p][w], lo, hi);
            flo[w] = lo; fhi[w] = hi;
            ps[2*p]   += lo; pq[2*p]   += lo*lo;
            ps[2*p+1] += hi; pq[2*p+1] += hi*hi;
        }
        vlo0 = make_float4(flo[0],flo[1],flo[2],flo[3]);
        vlo1 = make_float4(flo[4],flo[5],flo[6],flo[7]);
        vhi0 = make_float4(fhi[0],fhi[1],fhi[2],fhi[3]);
        vhi1 = make_float4(fhi[4],fhi[5],fhi[6],fhi[7]);
        int co = cg*8 + p*2;
        float* d0 = g_y1 + ((size_t)(b*128 + co  )*128 + h)*128 + wg*8;
        float* d1 = g_y1 + ((size_t)(b*128 + co+1)*128 + h)*128 + wg*8;
        *(float4*)(d0)   = vlo0; *(float4*)(d0+4) = vlo1;
        *(float4*)(d1)   = vhi0; *(float4*)(d1+4) = vhi1;
    }
    stat_reduce(ps, pq, wg, cg, g_s1, g_q1);
}

// ---------------- generic 1x1 conv with input transform ----------------
// mode 0: in = x*mod,           W = g_wsct, out = g_ysc, stats ssc/qsc
// mode 1: in = silu(a1*y1+b1),  W = g_w2t,  out = g_y2,  stats s2/q2
__global__ __launch_bounds__(256, 2) void k_conv1x1(const float* __restrict__ src,
                                                    float* __restrict__ dst,
                                                    float* Sacc, float* Qacc, int mode){
    int pc = blockIdx.x, b = blockIdx.y, tid = threadIdx.x;
    int wg = tid & 15, cg = tid >> 4;
    __shared__ __align__(16) float sW[2][128];
    __shared__ __align__(16) float sX[2][128];
    __shared__ float sA[128], sB[128];
    if (tid < 128){
        if (mode == 0){ sA[tid] = g_mod[b*128 + tid]; sB[tid] = 0.f; }
        else          { sA[tid] = g_a1[tid];          sB[tid] = g_b1[tid]; }
    }
    const float* wbase = mode ? g_w2t : g_wsct;
    const float* sbase = src + (size_t)(b*128)*16384 + pc*128;

    auto prefetch = [&](int ci, int buf){
        if (tid < 32)      cp16(&sW[buf][tid*4],      wbase + (size_t)ci*128 + tid*4);
        else if (tid < 64) cp16(&sX[buf][(tid-32)*4], sbase + (size_t)ci*16384 + (tid-32)*4);
        cp_commit();
    };

    u64 acc[4][8];
    #pragma unroll
    for (int p = 0; p < 4; p++)
        #pragma unroll
        for (int w = 0; w < 8; w++) acc[p][w] = 0ull;

    prefetch(0, 0);
    for (int ci = 0; ci < 128; ci++){
        int buf = ci & 1;
        __syncthreads();
        if (ci < 127){ prefetch(ci+1, buf^1); cp_wait1(); }
        else          { cp_wait0(); }
        __syncthreads();

        float a = sA[ci], bb = sB[ci];
        u64 xd[8];
        #pragma unroll
        for (int j = 0; j < 8; j++){
            float v = sX[buf][wg*8 + j];
            if (mode == 0) v = v * a;
            else           v = siluf(fmaf(a, v, bb));
            xd[j] = pack2(v, v);
        }
        const float* wrow = &sW[buf][cg*8];
        u64 w0 = *(const u64*)(wrow+0);
        u64 w1 = *(const u64*)(wrow+2);
        u64 w2 = *(const u64*)(wrow+4);
        u64 w3 = *(const u64*)(wrow+6);
        #pragma unroll
        for (int w = 0; w < 8; w++){
            acc[0][w] = ffma2(w0, xd[w], acc[0][w]);
            acc[1][w] = ffma2(w1, xd[w], acc[1][w]);
            acc[2][w] = ffma2(w2, xd[w], acc[2][w]);
            acc[3][w] = ffma2(w3, xd[w], acc[3][w]);
        }
    }

    float ps[8] = {0,0,0,0,0,0,0,0}, pq[8] = {0,0,0,0,0,0,0,0};
    #pragma unroll
    for (int p = 0; p < 4; p++){
        float lo, hi, flo[8], fhi[8];
        #pragma unroll
        for (int w = 0; w < 8; w++){
            unpack2(acc[p][w], lo, hi);
            flo[w] = lo; fhi[w] = hi;
            ps[2*p]   += lo; pq[2*p]   += lo*lo;
            ps[2*p+1] += hi; pq[2*p+1] += hi*hi;
        }
        int co = cg*8 + p*2;
        float* d0 = dst + (size_t)(b*128 + co  )*16384 + pc*128 + wg*8;
        float* d1 = dst + (size_t)(b*128 + co+1)*16384 + pc*128 + wg*8;
        *(float4*)(d0)   = make_float4(flo[0],flo[1],flo[2],flo[3]);
        *(float4*)(d0+4) = make_float4(flo[4],flo[5],flo[6],flo[7]);
        *(float4*)(d1)   = make_float4(fhi[0],fhi[1],fhi[2],fhi[3]);
        *(float4*)(d1+4) = make_float4(fhi[4],fhi[5],fhi[6],fhi[7]);
    }
    stat_reduce(ps, pq, wg, cg, Sacc, Qacc);
}

// ---------------- BN affine coefficients ----------------
__global__ void k_coefA(const float* g1, const float* be1, const float* gs, const float* bs){
    int c = threadIdx.x;
    float m = g_s1[c]/NSTATF, v = g_q1[c]/NSTATF - m*m;
    float a = g1[c] * rsqrtf(v + 1e-5f);
    g_a1[c] = a; g_b1[c] = be1[c] - m*a;
    m = g_ssc[c]/NSTATF; v = g_qsc[c]/NSTATF - m*m;
    a = gs[c] * rsqrtf(v + 1e-5f);
    g_asc[c] = a; g_bsc[c] = bs[c] - m*a;
}
__global__ void k_coefB(const float* g2, const float* be2){
    int c = threadIdx.x;
    float m = g_s2[c]/NSTATF, v = g_q2[c]/NSTATF - m*m;
    float a = g2[c] * rsqrtf(v + 1e-5f);
    g_a2[c] = a; g_b2[c] = be2[c] - m*a;
}

// ---------------- final: out = silu(bn2(y2) + bnsc(ysc)) ----------------
__global__ __launch_bounds__(256) void k_final(float* __restrict__ out){
    const float4* y2 = (const float4*)g_y2;
    const float4* ys = (const float4*)g_ysc;
    float4* o = (float4*)out;
    int n4 = NTOT/4;
    for (int i = blockIdx.x*blockDim.x + threadIdx.x; i < n4; i += blockDim.x*gridDim.x){
        int c = (i >> 12) & 127;           // float4 idx: 4096 per channel plane
        float a2 = g_a2[c], b2 = g_b2[c], as = g_asc[c], bs = g_bsc[c];
        float4 v2 = y2[i], vs = ys[i], r;
        float t;
        t = fmaf(a2, v2.x, b2) + fmaf(as, vs.x, bs); r.x = siluf(t);
        t = fmaf(a2, v2.y, b2) + fmaf(as, vs.y, bs); r.y = siluf(t);
        t = fmaf(a2, v2.z, b2) + fmaf(as, vs.z, bs); r.z = siluf(t);
        t = fmaf(a2, v2.w, b2) + fmaf(as, vs.w, bs); r.w = siluf(t);
        o[i] = r;
    }
}

// ---------------- launch ----------------
extern "C" void kernel_launch(void* const* d_in, const int* in_sizes, int n_in,
                              void* d_out, int out_size){
    const float* x      = (const float*)d_in[0];
    const float* dce    = (const float*)d_in[1];
    const float* dwc    = (const float*)d_in[2];
    const float* Wd1    = (const float*)d_in[3];
    const float* bd1    = (const float*)d_in[4];
    const float* Wd2    = (const float*)d_in[5];
    const float* bd2    = (const float*)d_in[6];
    const float* Wsh    = (const float*)d_in[7];
    const float* bsh    = (const float*)d_in[8];
    const float* Wex    = (const float*)d_in[9];
    const float* bex    = (const float*)d_in[10];
    const float* c1w    = (const float*)d_in[11];
    const float* bn1g   = (const float*)d_in[12];
    const float* bn1b   = (const float*)d_in[13];
    const float* c2w    = (const float*)d_in[14];
    const float* bn2g   = (const float*)d_in[15];
    const float* bn2b   = (const float*)d_in[16];
    const float* scw    = (const float*)d_in[17];
    const float* bnscg  = (const float*)d_in[18];
    const float* bnscb  = (const float*)d_in[19];
    float* out = (float*)d_out;

    float *y1, *ysc, *y2, *Ssc, *Qsc, *S2, *Q2;
    cudaGetSymbolAddress((void**)&y1,  g_y1);
    cudaGetSymbolAddress((void**)&ysc, g_ysc);
    cudaGetSymbolAddress((void**)&y2,  g_y2);
    cudaGetSymbolAddress((void**)&Ssc, g_ssc);
    cudaGetSymbolAddress((void**)&Qsc, g_qsc);
    cudaGetSymbolAddress((void**)&S2,  g_s2);
    cudaGetSymbolAddress((void**)&Q2,  g_q2);

    k_init<<<576, 256>>>(c1w, c2w, scw);
    k_dce1<<<dim3(8,16), 128>>>(dce, Wd1);
    k_dce2<<<16, 128>>>(bd1, Wd2, bd2);
    k_spatial<<<dim3(128,16), 256>>>(x, dwc);
    k_mod<<<16, 128>>>(Wsh, bsh, Wex, bex);
    k_conv3<<<dim3(128,16), 256>>>(x);
    k_conv1x1<<<dim3(128,16), 256>>>(x, ysc, Ssc, Qsc, 0);
    k_coefA<<<1, 128>>>(bn1g, bn1b, bnscg, bnscb);
    k_conv1x1<<<dim3(128,16), 256>>>(y1, y2, S2, Q2, 1);
    k_coefB<<<1, 128>>>(bn2g, bn2b);
    k_final<<<8192, 256>>>(out);
}

// round 16
// speedup vs baseline: 1.0002x; 1.0002x over previous
#include <cuda_runtime.h>
#include <cuda_bf16.h>

typedef unsigned long long u64;
#define NSTATF 262144.0f   // 16*128*128 per-channel count
#define NTOT   33554432

// ---------------- device scratch ----------------
__device__ __align__(256) float g_y1 [NTOT];
__device__ __align__(256) float g_ysc[NTOT];
__device__ __align__(256) float g_y2 [NTOT];
__device__ __align__(256) float g_w1t [147456];  // [ci][tap][co]
__device__ __align__(256) float g_wsct[16384];   // [ci][co]
__device__ __align__(256) float g_w2t [16384];   // [ci][co]
__device__ float g_dcepart[16384];               // [8][16][128]
__device__ float g_dce[2048], g_spatial[2048], g_mod[2048];
__device__ float g_s1[128], g_q1[128], g_ssc[128], g_qsc[128], g_s2[128], g_q2[128];
__device__ float g_a1[128], g_b1[128], g_asc[128], g_bsc[128], g_a2[128], g_b2[128];

// ---------------- helpers ----------------
__device__ __forceinline__ u64 pack2(float lo, float hi){
    u64 r; asm("mov.b64 %0, {%1, %2};" : "=l"(r) : "f"(lo), "f"(hi)); return r;
}
__device__ __forceinline__ void unpack2(u64 v, float& lo, float& hi){
    asm("mov.b64 {%0, %1}, %2;" : "=f"(lo), "=f"(hi) : "l"(v));
}
__device__ __forceinline__ u64 ffma2(u64 a, u64 b, u64 c){
    u64 d; asm("fma.rn.f32x2 %0, %1, %2, %3;" : "=l"(d) : "l"(a), "l"(b), "l"(c)); return d;
}
__device__ __forceinline__ void cp16(void* dst, const void* src){
    unsigned sa = (unsigned)__cvta_generic_to_shared(dst);
    asm volatile("cp.async.cg.shared.global [%0], [%1], 16;" :: "r"(sa), "l"(src) : "memory");
}
__device__ __forceinline__ void cp_commit(){ asm volatile("cp.async.commit_group;" ::: "memory"); }
__device__ __forceinline__ void cp_wait1(){ asm volatile("cp.async.wait_group 1;" ::: "memory"); }
__device__ __forceinline__ void cp_wait0(){ asm volatile("cp.async.wait_group 0;" ::: "memory"); }
__device__ __forceinline__ float geluf(float v){ return 0.5f*v*(1.f + erff(v*0.70710678f)); }
__device__ __forceinline__ float siluf(float v){ return v / (1.f + __expf(-v)); }

// stats reduce: 8 channel partial sums across 16 consecutive lanes, then atomics
__device__ __forceinline__ void stat_reduce(float* ps, float* pq, int wg, int cg,
                                            float* S, float* Q){
    #pragma unroll
    for (int o = 8; o; o >>= 1){
        #pragma unroll
        for (int k = 0; k < 8; k++){
            ps[k] += __shfl_xor_sync(0xffffffffu, ps[k], o, 16);
            pq[k] += __shfl_xor_sync(0xffffffffu, pq[k], o, 16);
        }
    }
    if (wg == 0){
        #pragma unroll
        for (int k = 0; k < 8; k++){
            atomicAdd(&S[cg*8+k], ps[k]);
            atomicAdd(&Q[cg*8+k], pq[k]);
        }
    }
}

// ---------------- K_init: weight transposes + zero stats ----------------
__global__ void k_init(const float* __restrict__ c1w, const float* __restrict__ c2w,
                       const float* __restrict__ scw){
    int i = blockIdx.x * blockDim.x + threadIdx.x;
    int n = blockDim.x * gridDim.x;
    for (int d = i; d < 147456; d += n){
        int co = d & 127, tap = (d >> 7) % 9, ci = d / 1152;
        g_w1t[d] = c1w[(co*128 + ci)*9 + tap];
    }
    for (int d = i; d < 16384; d += n){
        int co = d & 127, ci = d >> 7;
        g_w2t[d]  = c2w[co*128 + ci];
        g_wsct[d] = scw[co*128 + ci];
    }
    if (i < 128){ g_s1[i]=0.f; g_q1[i]=0.f; g_ssc[i]=0.f; g_qsc[i]=0.f; g_s2[i]=0.f; g_q2[i]=0.f; }
}

// ---------------- DCE FFN ----------------
__global__ __launch_bounds__(128) void k_dce1(const float* __restrict__ dce,
                                              const float* __restrict__ W1){
    int kb = blockIdx.x, b = blockIdx.y, c = threadIdx.x;
    __shared__ float sd[1600];
    const float* src = dce + b*12800 + kb*1600;
    for (int i = c; i < 1600; i += 128) sd[i] = src[i];
    __syncthreads();
    const float* wp = W1 + (size_t)kb*1600*128 + c;
    float acc = 0.f;
    #pragma unroll 8
    for (int k = 0; k < 1600; k++) acc = fmaf(sd[k], wp[(size_t)k*128], acc);
    g_dcepart[(kb*16 + b)*128 + c] = acc;
}

__global__ __launch_bounds__(128) void k_dce2(const float* __restrict__ b1,
                                              const float* __restrict__ W2,
                                              const float* __restrict__ b2){
    int b = blockIdx.x, c = threadIdx.x;
    __shared__ float sh[128];
    float acc = b1[c];
    #pragma unroll
    for (int kb = 0; kb < 8; kb++) acc += g_dcepart[(kb*16 + b)*128 + c];
    sh[c] = geluf(acc);
    __syncthreads();
    float f = b2[c];
    #pragma unroll 4
    for (int k = 0; k < 128; k++) f = fmaf(sh[k], W2[k*128 + c], f);
    g_dce[b*128 + c] = f;
}

// ---------------- spatial mean of padded depthwise 3x3 via rectangle sums ----------------
__global__ __launch_bounds__(256) void k_spatial(const float* __restrict__ x,
                                                 const float* __restrict__ dw){
    int c = blockIdx.x, b = blockIdx.y, tid = threadIdx.x;
    const float* base = x + (size_t)(b*128 + c) * 16384;
    const float4* xf = (const float4*)base;
    float tot=0.f, r0=0.f, rl=0.f, c0=0.f, cl=0.f;
    for (int i = tid; i < 4096; i += 256){
        float4 v = xf[i];
        float s = v.x + v.y + v.z + v.w;
        int row = i >> 5;
        tot += s;
        if (row == 0)       r0 += s;
        if (row == 127)     rl += s;
        if ((i & 31) == 0)  c0 += v.x;
        if ((i & 31) == 31) cl += v.w;
    }
    __shared__ float red[5][256];
    red[0][tid]=tot; red[1][tid]=r0; red[2][tid]=rl; red[3][tid]=c0; red[4][tid]=cl;
    __syncthreads();
    for (int s = 128; s > 0; s >>= 1){
        if (tid < s){
            #pragma unroll
            for (int a = 0; a < 5; a++) red[a][tid] += red[a][tid + s];
        }
        __syncthreads();
    }
    if (tid == 0){
        float T=red[0][0], R0=red[1][0], RL=red[2][0], C0=red[3][0], CL=red[4][0];
        float x00 = base[0], x0w = base[127], xh0 = base[127*128], xhw = base[127*128+127];
        float sp = 0.f;
        #pragma unroll
        for (int ky = 0; ky < 3; ky++){
            #pragma unroll
            for (int kx = 0; kx < 3; kx++){
                float rE = (ky==0) ? RL : (ky==2) ? R0 : 0.f;
                float cE = (kx==0) ? CL : (kx==2) ? C0 : 0.f;
                float crn = 0.f;
                if (ky==0 && kx==0) crn = xhw;
                else if (ky==0 && kx==2) crn = xh0;
                else if (ky==2 && kx==0) crn = x0w;
                else if (ky==2 && kx==2) crn = x00;
                sp += dw[c*9 + ky*3 + kx] * (T - rE - cE + crn);
            }
        }
        g_spatial[b*128 + c] = sp * (1.f/16384.f);
    }
}

// ---------------- SE modulation ----------------
__global__ __launch_bounds__(128) void k_mod(const float* __restrict__ Wsh, const float* __restrict__ bsh,
                                             const float* __restrict__ Wex, const float* __restrict__ bex){
    int b = blockIdx.x, c = threadIdx.x;
    __shared__ float sm[128], ss[64];
    sm[c] = g_dce[b*128 + c] * g_spatial[b*128 + c];
    __syncthreads();
    if (c < 64){
        float t = bsh[c];
        #pragma unroll 4
        for (int k = 0; k < 128; k++) t = fmaf(sm[k], Wsh[k*64 + c], t);
        ss[c] = geluf(t);
    }
    __syncthreads();
    float u = bex[c];
    #pragma unroll 4
    for (int j = 0; j < 64; j++) u = fmaf(ss[j], Wex[j*128 + c], u);
    g_mod[b*128 + c] = 1.f / (1.f + __expf(-u));
}

// ---------------- conv3x3 (the heavy kernel): y1 = conv3x3(x*mod), + stats ----------------
__global__ __launch_bounds__(256, 2) void k_conv3(const float* __restrict__ x){
    int h = blockIdx.x, b = blockIdx.y, tid = threadIdx.x;
    int wg = tid & 15, cg = tid >> 4;         // 16 w-groups x 16 co-groups
    __shared__ __align__(16) float sW[2][9][128];
    __shared__ __align__(16) float sX[2][3][128];
    __shared__ float sMod[128];
    if (tid < 128) sMod[tid] = g_mod[b*128 + tid];
    bool v0 = (h > 0), v2 = (h < 127);
    const float* xb = x + (size_t)(b*128) * 16384;

    auto prefetch = [&](int ci, int buf){
        const float* wsrc = g_w1t + (size_t)ci * 1152;
        cp16(&sW[buf][0][0] + tid*4, wsrc + tid*4);
        if (tid < 32) cp16(&sW[buf][0][0] + (tid+256)*4, wsrc + (tid+256)*4);
        if (tid < 96){
            int r = tid >> 5, ch = tid & 31;
            int row = h - 1 + r;
            if (row >= 0 && row < 128)
                cp16(&sX[buf][r][ch*4], xb + (size_t)ci*16384 + row*128 + ch*4);
        }
        cp_commit();
    };

    u64 acc[4][8];
    #pragma unroll
    for (int p = 0; p < 4; p++)
        #pragma unroll
        for (int w = 0; w < 8; w++) acc[p][w] = 0ull;

    prefetch(0, 0);
    for (int ci = 0; ci < 128; ci++){
        int buf = ci & 1;
        __syncthreads();                       // prior iter done reading buf^1
        if (ci < 127){ prefetch(ci+1, buf^1); cp_wait1(); }
        else          { cp_wait0(); }
        __syncthreads();                       // this iter's data visible

        float s = sMod[ci];
        #pragma unroll
        for (int ky = 0; ky < 3; ky++){
            bool valid = (ky==0) ? v0 : ((ky==2) ? v2 : true);
            u64 xd[10];
            #pragma unroll
            for (int j = 0; j < 10; j++){
                int idx = wg*8 - 1 + j;
                float v = 0.f;
                if (valid && idx >= 0 && idx < 128) v = sX[buf][ky][idx] * s;
                xd[j] = pack2(v, v);
            }
            #pragma unroll
            for (int kx = 0; kx < 3; kx++){
                const float* wrow = &sW[buf][ky*3+kx][cg*8];
                u64 w0 = *(const u64*)(wrow+0);
                u64 w1 = *(const u64*)(wrow+2);
                u64 w2 = *(const u64*)(wrow+4);
                u64 w3 = *(const u64*)(wrow+6);
                #pragma unroll
                for (int w = 0; w < 8; w++){
                    acc[0][w] = ffma2(w0, xd[w+kx], acc[0][w]);
                    acc[1][w] = ffma2(w1, xd[w+kx], acc[1][w]);
                    acc[2][w] = ffma2(w2, xd[w+kx], acc[2][w]);
                    acc[3][w] = ffma2(w3, xd[w+kx], acc[3][w]);
                }
            }
        }
    }

    // stats + store
    float ps[8] = {0,0,0,0,0,0,0,0}, pq[8] = {0,0,0,0,0,0,0,0};
    #pragma unroll
    for (int p = 0; p < 4; p++){
        float lo, hi;
        float4 vlo0, vlo1, vhi0, vhi1;
        float flo[8], fhi[8];
        #pragma unroll
        for (int w = 0; w < 8; w++){
            unpack2(acc[p][w], lo, hi);
            flo[w] = lo; fhi[w] = hi;
            ps[2*p]   += lo; pq[2*p]   += lo*lo;
            ps[2*p+1] += hi; pq[2*p+1] += hi*hi;
        }
        vlo0 = make_float4(flo[0],flo[1],flo[2],flo[3]);
        vlo1 = make_float4(flo[4],flo[5],flo[6],flo[7]);
        vhi0 = make_float4(fhi[0],fhi[1],fhi[2],fhi[3]);
        vhi1 = make_float4(fhi[4],fhi[5],fhi[6],fhi[7]);
        int co = cg*8 + p*2;
        float* d0 = g_y1 + ((size_t)(b*128 + co  )*128 + h)*128 + wg*8;
        float* d1 = g_y1 + ((size_t)(b*128 + co+1)*128 + h)*128 + wg*8;
        *(float4*)(d0)   = vlo0; *(float4*)(d0+4) = vlo1;
        *(float4*)(d1)   = vhi0; *(float4*)(d1+4) = vhi1;
    }
    stat_reduce(ps, pq, wg, cg, g_s1, g_q1);
}

// ---------------- generic 1x1 conv with input transform ----------------
// mode 0: in = x*mod,           W = g_wsct, out = g_ysc, stats ssc/qsc
// mode 1: in = silu(a1*y1+b1),  W = g_w2t,  out = g_y2,  stats s2/q2
__global__ __launch_bounds__(256, 2) void k_conv1x1(const float* __restrict__ src,
                                                    float* __restrict__ dst,
                                                    float* Sacc, float* Qacc, int mode){
    int pc = blockIdx.x, b = blockIdx.y, tid = threadIdx.x;
    int wg = tid & 15, cg = tid >> 4;
    __shared__ __align__(16) float sW[2][128];
    __shared__ __align__(16) float sX[2][128];
    __shared__ float sA[128], sB[128];
    if (tid < 128){
        if (mode == 0){ sA[tid] = g_mod[b*128 + tid]; sB[tid] = 0.f; }
        else          { sA[tid] = g_a1[tid];          sB[tid] = g_b1[tid]; }
    }
    const float* wbase = mode ? g_w2t : g_wsct;
    const float* sbase = src + (size_t)(b*128)*16384 + pc*128;

    auto prefetch = [&](int ci, int buf){
        if (tid < 32)      cp16(&sW[buf][tid*4],      wbase + (size_t)ci*128 + tid*4);
        else if (tid < 64) cp16(&sX[buf][(tid-32)*4], sbase + (size_t)ci*16384 + (tid-32)*4);
        cp_commit();
    };

    u64 acc[4][8];
    #pragma unroll
    for (int p = 0; p < 4; p++)
        #pragma unroll
        for (int w = 0; w < 8; w++) acc[p][w] = 0ull;

    prefetch(0, 0);
    for (int ci = 0; ci < 128; ci++){
        int buf = ci & 1;
        __syncthreads();
        if (ci < 127){ prefetch(ci+1, buf^1); cp_wait1(); }
        else          { cp_wait0(); }
        __syncthreads();

        float a = sA[ci], bb = sB[ci];
        u64 xd[8];
        #pragma unroll
        for (int j = 0; j < 8; j++){
            float v = sX[buf][wg*8 + j];
            if (mode == 0) v = v * a;
            else           v = siluf(fmaf(a, v, bb));
            xd[j] = pack2(v, v);
        }
        const float* wrow = &sW[buf][cg*8];
        u64 w0 = *(const u64*)(wrow+0);
        u64 w1 = *(const u64*)(wrow+2);
        u64 w2 = *(const u64*)(wrow+4);
        u64 w3 = *(const u64*)(wrow+6);
        #pragma unroll
        for (int w = 0; w < 8; w++){
            acc[0][w] = ffma2(w0, xd[w], acc[0][w]);
            acc[1][w] = ffma2(w1, xd[w], acc[1][w]);
            acc[2][w] = ffma2(w2, xd[w], acc[2][w]);
            acc[3][w] = ffma2(w3, xd[w], acc[3][w]);
        }
    }

    float ps[8] = {0,0,0,0,0,0,0,0}, pq[8] = {0,0,0,0,0,0,0,0};
    #pragma unroll
    for (int p = 0; p < 4; p++){
        float lo, hi, flo[8], fhi[8];
        #pragma unroll
        for (int w = 0; w < 8; w++){
            unpack2(acc[p][w], lo, hi);
            flo[w] = lo; fhi[w] = hi;
            ps[2*p]   += lo; pq[2*p]   += lo*lo;
            ps[2*p+1] += hi; pq[2*p+1] += hi*hi;
        }
        int co = cg*8 + p*2;
        float* d0 = dst + (size_t)(b*128 + co  )*16384 + pc*128 + wg*8;
        float* d1 = dst + (size_t)(b*128 + co+1)*16384 + pc*128 + wg*8;
        *(float4*)(d0)   = make_float4(flo[0],flo[1],flo[2],flo[3]);
        *(float4*)(d0+4) = make_float4(flo[4],flo[5],flo[6],flo[7]);
        *(float4*)(d1)   = make_float4(fhi[0],fhi[1],fhi[2],fhi[3]);
        *(float4*)(d1+4) = make_float4(fhi[4],fhi[5],fhi[6],fhi[7]);
    }
    stat_reduce(ps, pq, wg, cg, Sacc, Qacc);
}

// ---------------- BN affine coefficients ----------------
__global__ void k_coefA(const float* g1, const float* be1, const float* gs, const float* bs){
    int c = threadIdx.x;
    float m = g_s1[c]/NSTATF, v = g_q1[c]/NSTATF - m*m;
    float a = g1[c] * rsqrtf(v + 1e-5f);
    g_a1[c] = a; g_b1[c] = be1[c] - m*a;
    m = g_ssc[c]/NSTATF; v = g_qsc[c]/NSTATF - m*m;
    a = gs[c] * rsqrtf(v + 1e-5f);
    g_asc[c] = a; g_bsc[c] = bs[c] - m*a;
}
__global__ void k_coefB(const float* g2, const float* be2){
    int c = threadIdx.x;
    float m = g_s2[c]/NSTATF, v = g_q2[c]/NSTATF - m*m;
    float a = g2[c] * rsqrtf(v + 1e-5f);
    g_a2[c] = a; g_b2[c] = be2[c] - m*a;
}

// ---------------- final: out = silu(bn2(y2) + bnsc(ysc)) ----------------
__global__ __launch_bounds__(256) void k_final(float* __restrict__ out){
    const float4* y2 = (const float4*)g_y2;
    const float4* ys = (const float4*)g_ysc;
    float4* o = (float4*)out;
    int n4 = NTOT/4;
    for (int i = blockIdx.x*blockDim.x + threadIdx.x; i < n4; i += blockDim.x*gridDim.x){
        int c = (i >> 12) & 127;           // float4 idx: 4096 per channel plane
        float a2 = g_a2[c], b2 = g_b2[c], as = g_asc[c], bs = g_bsc[c];
        float4 v2 = y2[i], vs = ys[i], r;
        float t;
        t = fmaf(a2, v2.x, b2) + fmaf(as, vs.x, bs); r.x = siluf(t);
        t = fmaf(a2, v2.y, b2) + fmaf(as, vs.y, bs); r.y = siluf(t);
        t = fmaf(a2, v2.z, b2) + fmaf(as, vs.z, bs); r.z = siluf(t);
        t = fmaf(a2, v2.w, b2) + fmaf(as, vs.w, bs); r.w = siluf(t);
        o[i] = r;
    }
}

// ---------------- launch ----------------
extern "C" void kernel_launch(void* const* d_in, const int* in_sizes, int n_in,
                              void* d_out, int out_size){
    const float* x      = (const float*)d_in[0];
    const float* dce    = (const float*)d_in[1];
    const float* dwc    = (const float*)d_in[2];
    const float* Wd1    = (const float*)d_in[3];
    const float* bd1    = (const float*)d_in[4];
    const float* Wd2    = (const float*)d_in[5];
    const float* bd2    = (const float*)d_in[6];
    const float* Wsh    = (const float*)d_in[7];
    const float* bsh    = (const float*)d_in[8];
    const float* Wex    = (const float*)d_in[9];
    const float* bex    = (const float*)d_in[10];
    const float* c1w    = (const float*)d_in[11];
    const float* bn1g   = (const float*)d_in[12];
    const float* bn1b   = (const float*)d_in[13];
    const float* c2w    = (const float*)d_in[14];
    const float* bn2g   = (const float*)d_in[15];
    const float* bn2b   = (const float*)d_in[16];
    const float* scw    = (const float*)d_in[17];
    const float* bnscg  = (const float*)d_in[18];
    const float* bnscb  = (const float*)d_in[19];
    float* out = (float*)d_out;

    float *y1, *ysc, *y2, *Ssc, *Qsc, *S2, *Q2;
    cudaGetSymbolAddress((void**)&y1,  g_y1);
    cudaGetSymbolAddress((void**)&ysc, g_ysc);
    cudaGetSymbolAddress((void**)&y2,  g_y2);
    cudaGetSymbolAddress((void**)&Ssc, g_ssc);
    cudaGetSymbolAddress((void**)&Qsc, g_qsc);
    cudaGetSymbolAddress((void**)&S2,  g_s2);
    cudaGetSymbolAddress((void**)&Q2,  g_q2);

    k_init<<<576, 256>>>(c1w, c2w, scw);
    k_dce1<<<dim3(8,16), 128>>>(dce, Wd1);
    k_dce2<<<16, 128>>>(bd1, Wd2, bd2);
    k_spatial<<<dim3(128,16), 256>>>(x, dwc);
    k_mod<<<16, 128>>>(Wsh, bsh, Wex, bex);
    k_conv3<<<dim3(128,16), 256>>>(x);
    k_conv1x1<<<dim3(128,16), 256>>>(x, ysc, Ssc, Qsc, 0);
    k_coefA<<<1, 128>>>(bn1g, bn1b, bnscg, bnscb);
    k_conv1x1<<<dim3(128,16), 256>>>(y1, y2, S2, Q2, 1);
    k_coefB<<<1, 128>>>(bn2g, bn2b);
    k_final<<<8192, 256>>>(out);
}

// round 17
// speedup vs baseline: 2.4922x; 2.4918x over previous
#include <cuda_runtime.h>
#include <cuda_bf16.h>

typedef unsigned int uint;
#define NSTATF 262144.0f
#define NTOT   33554432

// ---------------- device scratch ----------------
__device__ __align__(256) float g_xm [NTOT];
__device__ __align__(256) float g_y1 [NTOT];
__device__ __align__(256) float g_ysc[NTOT];
__device__ __align__(256) float g_y2 [NTOT];
__device__ __align__(256) uint  g_w1u[147456];   // [tap][ci][co] tf32
__device__ __align__(256) uint  g_wsu[16384];    // [ci][co] tf32
__device__ __align__(256) uint  g_w2u[16384];    // [ci][co] tf32
__device__ float g_dcepart[16384];
__device__ float g_dce[2048], g_spatial[2048], g_mod[2048];
__device__ float g_s1[128], g_q1[128], g_ssc[128], g_qsc[128], g_s2[128], g_q2[128];
__device__ float g_a1[128], g_b1[128], g_asc[128], g_bsc[128], g_a2[128], g_b2[128];

// ---------------- helpers ----------------
__device__ __forceinline__ uint tf32c(float f){
    uint r; asm("cvt.rna.tf32.f32 %0, %1;" : "=r"(r) : "f"(f)); return r;
}
__device__ __forceinline__ void mma8(float* d, const uint* a, uint b0, uint b1){
    asm volatile("mma.sync.aligned.m16n8k8.row.col.f32.tf32.tf32.f32 "
        "{%0,%1,%2,%3}, {%4,%5,%6,%7}, {%8,%9}, {%0,%1,%2,%3};"
        : "+f"(d[0]), "+f"(d[1]), "+f"(d[2]), "+f"(d[3])
        : "r"(a[0]), "r"(a[1]), "r"(a[2]), "r"(a[3]), "r"(b0), "r"(b1));
}
__device__ __forceinline__ void cp16(void* dst, const void* src){
    unsigned sa = (unsigned)__cvta_generic_to_shared(dst);
    asm volatile("cp.async.cg.shared.global [%0], [%1], 16;" :: "r"(sa), "l"(src) : "memory");
}
__device__ __forceinline__ void cp_commit(){ asm volatile("cp.async.commit_group;" ::: "memory"); }
__device__ __forceinline__ void cp_wait1(){ asm volatile("cp.async.wait_group 1;" ::: "memory"); }
__device__ __forceinline__ void cp_wait0(){ asm volatile("cp.async.wait_group 0;" ::: "memory"); }
__device__ __forceinline__ float geluf(float v){ return 0.5f*v*(1.f + erff(v*0.70710678f)); }
__device__ __forceinline__ float siluf(float v){ return v / (1.f + __expf(-v)); }

// epilogue: stats reduce over 4-lane groups (same g), atomics + stores
__device__ __forceinline__ void epilogue(float acc[2][8][4], int co0, int g, int lt, int ng,
                                         float* dst, long long pbase, int rowstride,
                                         float* S, float* Q){
    float sv[4] = {0,0,0,0}, qv[4] = {0,0,0,0};
    #pragma unroll
    for (int m = 0; m < 2; m++){
        long long b0 = pbase + (long long)(co0 + m*16 + g    ) * 16384;
        long long b1 = pbase + (long long)(co0 + m*16 + g + 8) * 16384;
        #pragma unroll
        for (int j = 0; j < 8; j++){
            float* a = acc[m][j];
            sv[m*2]   += a[0] + a[1];  qv[m*2]   += a[0]*a[0] + a[1]*a[1];
            sv[m*2+1] += a[2] + a[3];  qv[m*2+1] += a[2]*a[2] + a[3]*a[3];
            int px = ng*64 + j*8 + 2*lt;
            *(float2*)(dst + b0 + rowstride + px) = make_float2(a[0], a[1]);
            *(float2*)(dst + b1 + rowstride + px) = make_float2(a[2], a[3]);
        }
    }
    #pragma unroll
    for (int o = 1; o < 4; o <<= 1){
        #pragma unroll
        for (int k = 0; k < 4; k++){
            sv[k] += __shfl_xor_sync(0xffffffffu, sv[k], o, 4);
            qv[k] += __shfl_xor_sync(0xffffffffu, qv[k], o, 4);
        }
    }
    if (lt == 0){
        #pragma unroll
        for (int m = 0; m < 2; m++){
            atomicAdd(&S[co0+m*16+g],   sv[m*2]);   atomicAdd(&Q[co0+m*16+g],   qv[m*2]);
            atomicAdd(&S[co0+m*16+g+8], sv[m*2+1]); atomicAdd(&Q[co0+m*16+g+8], qv[m*2+1]);
        }
    }
}

// ---------------- K_init ----------------
__global__ void k_init(const float* __restrict__ c1w, const float* __restrict__ c2w,
                       const float* __restrict__ scw){
    int i = blockIdx.x * blockDim.x + threadIdx.x;
    int n = blockDim.x * gridDim.x;
    for (int d = i; d < 147456; d += n){
        int co = d & 127, ci = (d >> 7) & 127, tap = d >> 14;
        g_w1u[d] = tf32c(c1w[(co*128 + ci)*9 + tap]);
    }
    for (int d = i; d < 16384; d += n){
        int co = d & 127, ci = d >> 7;
        g_w2u[d] = tf32c(c2w[co*128 + ci]);
        g_wsu[d] = tf32c(scw[co*128 + ci]);
    }
    if (i < 128){ g_s1[i]=0.f; g_q1[i]=0.f; g_ssc[i]=0.f; g_qsc[i]=0.f; g_s2[i]=0.f; g_q2[i]=0.f; }
}

// ---------------- DCE FFN ----------------
__global__ __launch_bounds__(128) void k_dce1(const float* __restrict__ dce,
                                              const float* __restrict__ W1){
    int kb = blockIdx.x, b = blockIdx.y, c = threadIdx.x;
    __shared__ float sd[1600];
    const float* src = dce + b*12800 + kb*1600;
    for (int i = c; i < 1600; i += 128) sd[i] = src[i];
    __syncthreads();
    const float* wp = W1 + (size_t)kb*1600*128 + c;
    float acc = 0.f;
    #pragma unroll 8
    for (int k = 0; k < 1600; k++) acc = fmaf(sd[k], wp[(size_t)k*128], acc);
    g_dcepart[(kb*16 + b)*128 + c] = acc;
}

__global__ __launch_bounds__(128) void k_dce2(const float* __restrict__ b1,
                                              const float* __restrict__ W2,
                                              const float* __restrict__ b2){
    int b = blockIdx.x, c = threadIdx.x;
    __shared__ float sh[128];
    float acc = b1[c];
    #pragma unroll
    for (int kb = 0; kb < 8; kb++) acc += g_dcepart[(kb*16 + b)*128 + c];
    sh[c] = geluf(acc);
    __syncthreads();
    float f = b2[c];
    #pragma unroll 4
    for (int k = 0; k < 128; k++) f = fmaf(sh[k], W2[k*128 + c], f);
    g_dce[b*128 + c] = f;
}

// ---------------- spatial mean via rectangle sums ----------------
__global__ __launch_bounds__(256) void k_spatial(const float* __restrict__ x,
                                                 const float* __restrict__ dw){
    int c = blockIdx.x, b = blockIdx.y, tid = threadIdx.x;
    const float* base = x + (size_t)(b*128 + c) * 16384;
    const float4* xf = (const float4*)base;
    float tot=0.f, r0=0.f, rl=0.f, c0=0.f, cl=0.f;
    for (int i = tid; i < 4096; i += 256){
        float4 v = xf[i];
        float s = v.x + v.y + v.z + v.w;
        int row = i >> 5;
        tot += s;
        if (row == 0)       r0 += s;
        if (row == 127)     rl += s;
        if ((i & 31) == 0)  c0 += v.x;
        if ((i & 31) == 31) cl += v.w;
    }
    __shared__ float red[5][256];
    red[0][tid]=tot; red[1][tid]=r0; red[2][tid]=rl; red[3][tid]=c0; red[4][tid]=cl;
    __syncthreads();
    for (int s = 128; s > 0; s >>= 1){
        if (tid < s){
            #pragma unroll
            for (int a = 0; a < 5; a++) red[a][tid] += red[a][tid + s];
        }
        __syncthreads();
    }
    if (tid == 0){
        float T=red[0][0], R0=red[1][0], RL=red[2][0], C0=red[3][0], CL=red[4][0];
        float x00 = base[0], x0w = base[127], xh0 = base[127*128], xhw = base[127*128+127];
        float sp = 0.f;
        #pragma unroll
        for (int ky = 0; ky < 3; ky++){
            #pragma unroll
            for (int kx = 0; kx < 3; kx++){
                float rE = (ky==0) ? RL : (ky==2) ? R0 : 0.f;
                float cE = (kx==0) ? CL : (kx==2) ? C0 : 0.f;
                float crn = 0.f;
                if (ky==0 && kx==0) crn = xhw;
                else if (ky==0 && kx==2) crn = xh0;
                else if (ky==2 && kx==0) crn = x0w;
                else if (ky==2 && kx==2) crn = x00;
                sp += dw[c*9 + ky*3 + kx] * (T - rE - cE + crn);
            }
        }
        g_spatial[b*128 + c] = sp * (1.f/16384.f);
    }
}

// ---------------- SE modulation ----------------
__global__ __launch_bounds__(128) void k_mod(const float* __restrict__ Wsh, const float* __restrict__ bsh,
                                             const float* __restrict__ Wex, const float* __restrict__ bex){
    int b = blockIdx.x, c = threadIdx.x;
    __shared__ float sm[128], ss[64];
    sm[c] = g_dce[b*128 + c] * g_spatial[b*128 + c];
    __syncthreads();
    if (c < 64){
        float t = bsh[c];
        #pragma unroll 4
        for (int k = 0; k < 128; k++) t = fmaf(sm[k], Wsh[k*64 + c], t);
        ss[c] = geluf(t);
    }
    __syncthreads();
    float u = bex[c];
    #pragma unroll 4
    for (int j = 0; j < 64; j++) u = fmaf(ss[j], Wex[j*128 + c], u);
    g_mod[b*128 + c] = 1.f / (1.f + __expf(-u));
}

// ---------------- prep passes (write tf32 bit-patterns) ----------------
__global__ __launch_bounds__(256) void k_premul(const float* __restrict__ x){
    const float4* xi = (const float4*)x;
    float4* o = (float4*)g_xm;
    for (int i = blockIdx.x*blockDim.x + threadIdx.x; i < NTOT/4; i += blockDim.x*gridDim.x){
        int c = (i >> 12) & 127, b = i >> 19;
        float m = g_mod[b*128 + c];
        float4 v = xi[i], r;
        r.x = __uint_as_float(tf32c(v.x*m)); r.y = __uint_as_float(tf32c(v.y*m));
        r.z = __uint_as_float(tf32c(v.z*m)); r.w = __uint_as_float(tf32c(v.w*m));
        o[i] = r;
    }
}
__global__ __launch_bounds__(256) void k_prep2(){
    const float4* yi = (const float4*)g_y1;
    float4* o = (float4*)g_xm;
    for (int i = blockIdx.x*blockDim.x + threadIdx.x; i < NTOT/4; i += blockDim.x*gridDim.x){
        int c = (i >> 12) & 127;
        float a = g_a1[c], bb = g_b1[c];
        float4 v = yi[i], r;
        r.x = __uint_as_float(tf32c(siluf(fmaf(a, v.x, bb))));
        r.y = __uint_as_float(tf32c(siluf(fmaf(a, v.y, bb))));
        r.z = __uint_as_float(tf32c(siluf(fmaf(a, v.z, bb))));
        r.w = __uint_as_float(tf32c(siluf(fmaf(a, v.w, bb))));
        o[i] = r;
    }
}

// ---------------- conv3x3 implicit-GEMM (tf32 mma) ----------------
#define C3_SMEM ((2*9*4*136 + 2*3*4*136)*4)
__global__ __launch_bounds__(256, 2) void k_conv3(){
    int h = blockIdx.x, b = blockIdx.y, tid = threadIdx.x;
    int warp = tid >> 5, lane = tid & 31;
    int g = lane >> 2, lt = lane & 3;
    int co0 = (warp >> 1) * 32, ng = warp & 1;
    extern __shared__ uint dsm[];
    uint* swp = dsm;                 // [2][9][4][136]
    uint* sxp = dsm + 2*9*4*136;     // [2][3][4][136]
    #define SW3(bf,t,r,i) swp[((((bf)*9+(t))*4+(r))*136)+(i)]
    #define SX3(bf,k,r,i) sxp[((((bf)*3+(k))*4+(r))*136)+(i)]
    const int KY[9] = {0,0,0,1,1,1,2,2,2};
    const int KX[9] = {0,1,2,0,1,2,0,1,2};

    for (int i = tid; i < 2*3*4*136; i += 256) sxp[i] = 0u;
    __syncthreads();

    const float* xm = g_xm + (size_t)b * 2097152;
    auto prefetch = [&](int cc, int buf){
        int ci0 = cc * 4;
        #pragma unroll
        for (int it = 0; it < 5; it++){
            int idx = tid + it*256;
            if (idx < 1152){
                int seg = idx >> 5, off = (idx & 31) * 4;
                int tap = seg >> 2, r = seg & 3;
                cp16(&SW3(buf, tap, r, off), g_w1u + ((tap*128 + ci0 + r) << 7) + off);
            }
        }
        #pragma unroll
        for (int it = 0; it < 2; it++){
            int idx = tid + it*256;
            if (idx < 384){
                int seg = idx >> 5, off = (idx & 31) * 4;
                int ky = seg >> 2, r = seg & 3;
                int row = h - 1 + ky;
                if (row >= 0 && row < 128)
                    cp16(&SX3(buf, ky, r, 4 + off), xm + ((size_t)(ci0 + r) << 14) + (row << 7) + off);
            }
        }
        cp_commit();
    };

    float acc[2][8][4];
    #pragma unroll
    for (int m = 0; m < 2; m++)
        #pragma unroll
        for (int j = 0; j < 8; j++)
            #pragma unroll
            for (int k = 0; k < 4; k++) acc[m][j][k] = 0.f;

    prefetch(0, 0);
    for (int cc = 0; cc < 32; cc++){
        int buf = cc & 1;
        __syncthreads();
        if (cc < 31){ prefetch(cc+1, buf^1); cp_wait1(); } else cp_wait0();
        __syncthreads();

        #pragma unroll
        for (int p = 0; p < 5; p++){
            int t0 = 2*p, t1 = 2*p + 1;
            bool last = (p == 4);
            uint aA[2][4];
            #pragma unroll
            for (int m = 0; m < 2; m++){
                int cb = co0 + m*16;
                aA[m][0] = SW3(buf, t0, lt, cb + g);
                aA[m][1] = SW3(buf, t0, lt, cb + g + 8);
                aA[m][2] = last ? 0u : SW3(buf, t1, lt, cb + g);
                aA[m][3] = last ? 0u : SW3(buf, t1, lt, cb + g + 8);
            }
            #pragma unroll
            for (int j = 0; j < 8; j++){
                int n8 = ng*64 + j*8;
                uint b0 = SX3(buf, KY[t0], lt, 3 + n8 + g + KX[t0]);
                uint b1 = last ? 0u : SX3(buf, KY[t1], lt, 3 + n8 + g + KX[t1]);
                mma8(acc[0][j], aA[0], b0, b1);
                mma8(acc[1][j], aA[1], b0, b1);
            }
        }
    }
    epilogue(acc, co0, g, lt, ng, g_y1, (long long)b * 2097152, h << 7, g_s1, g_q1);
}

// ---------------- generic 1x1 GEMM (tf32 mma) ----------------
__global__ __launch_bounds__(256, 4) void k_gemm(const float* __restrict__ in,
                                                 const uint* __restrict__ w,
                                                 float* __restrict__ dst,
                                                 float* S, float* Q){
    int pc = blockIdx.x, b = blockIdx.y, tid = threadIdx.x;
    int warp = tid >> 5, lane = tid & 31;
    int g = lane >> 2, lt = lane & 3;
    int co0 = (warp >> 1) * 32, ng = warp & 1;
    __shared__ uint sxin[2][8][136];
    __shared__ uint swm [2][8][136];

    const float* src = in + (size_t)b * 2097152 + pc * 128;
    auto prefetch = [&](int cc, int buf){
        int k0 = cc * 8;
        int seg = tid >> 5, off = (tid & 31) * 4;
        cp16(&sxin[buf][seg][off], src + ((size_t)(k0 + seg) << 14) + off);
        cp16(&swm [buf][seg][off], w + ((k0 + seg) << 7) + off);
        cp_commit();
    };

    float acc[2][8][4];
    #pragma unroll
    for (int m = 0; m < 2; m++)
        #pragma unroll
        for (int j = 0; j < 8; j++)
            #pragma unroll
            for (int k = 0; k < 4; k++) acc[m][j][k] = 0.f;

    prefetch(0, 0);
    for (int cc = 0; cc < 16; cc++){
        int buf = cc & 1;
        __syncthreads();
        if (cc < 15){ prefetch(cc+1, buf^1); cp_wait1(); } else cp_wait0();
        __syncthreads();

        uint aA[2][4];
        #pragma unroll
        for (int m = 0; m < 2; m++){
            int cb = co0 + m*16;
            aA[m][0] = swm[buf][lt    ][cb + g];
            aA[m][1] = swm[buf][lt    ][cb + g + 8];
            aA[m][2] = swm[buf][lt + 4][cb + g];
            aA[m][3] = swm[buf][lt + 4][cb + g + 8];
        }
        #pragma unroll
        for (int j = 0; j < 8; j++){
            int n8 = ng*64 + j*8;
            uint b0 = sxin[buf][lt    ][n8 + g];
            uint b1 = sxin[buf][lt + 4][n8 + g];
            mma8(acc[0][j], aA[0], b0, b1);
            mma8(acc[1][j], aA[1], b0, b1);
        }
    }
    epilogue(acc, co0, g, lt, ng, dst, (long long)b * 2097152, pc << 7, S, Q);
}

// ---------------- BN coefficients ----------------
__global__ void k_coefA(const float* g1, const float* be1, const float* gs, const float* bs){
    int c = threadIdx.x;
    float m = g_s1[c]/NSTATF, v = g_q1[c]/NSTATF - m*m;
    float a = g1[c] * rsqrtf(v + 1e-5f);
    g_a1[c] = a; g_b1[c] = be1[c] - m*a;
    m = g_ssc[c]/NSTATF; v = g_qsc[c]/NSTATF - m*m;
    a = gs[c] * rsqrtf(v + 1e-5f);
    g_asc[c] = a; g_bsc[c] = bs[c] - m*a;
}
__global__ void k_coefB(const float* g2, const float* be2){
    int c = threadIdx.x;
    float m = g_s2[c]/NSTATF, v = g_q2[c]/NSTATF - m*m;
    float a = g2[c] * rsqrtf(v + 1e-5f);
    g_a2[c] = a; g_b2[c] = be2[c] - m*a;
}

// ---------------- final ----------------
__global__ __launch_bounds__(256) void k_final(float* __restrict__ out){
    const float4* y2 = (const float4*)g_y2;
    const float4* ys = (const float4*)g_ysc;
    float4* o = (float4*)out;
    for (int i = blockIdx.x*blockDim.x + threadIdx.x; i < NTOT/4; i += blockDim.x*gridDim.x){
        int c = (i >> 12) & 127;
        float a2 = g_a2[c], b2 = g_b2[c], as = g_asc[c], bs = g_bsc[c];
        float4 v2 = y2[i], vs = ys[i], r;
        float t;
        t = fmaf(a2, v2.x, b2) + fmaf(as, vs.x, bs); r.x = siluf(t);
        t = fmaf(a2, v2.y, b2) + fmaf(as, vs.y, bs); r.y = siluf(t);
        t = fmaf(a2, v2.z, b2) + fmaf(as, vs.z, bs); r.z = siluf(t);
        t = fmaf(a2, v2.w, b2) + fmaf(as, vs.w, bs); r.w = siluf(t);
        o[i] = r;
    }
}

// ---------------- launch ----------------
extern "C" void kernel_launch(void* const* d_in, const int* in_sizes, int n_in,
                              void* d_out, int out_size){
    const float* x    = (const float*)d_in[0];
    const float* dce  = (const float*)d_in[1];
    const float* dwc  = (const float*)d_in[2];
    const float* Wd1  = (const float*)d_in[3];
    const float* bd1  = (const float*)d_in[4];
    const float* Wd2  = (const float*)d_in[5];
    const float* bd2  = (const float*)d_in[6];
    const float* Wsh  = (const float*)d_in[7];
    const float* bsh  = (const float*)d_in[8];
    const float* Wex  = (const float*)d_in[9];
    const float* bex  = (const float*)d_in[10];
    const float* c1w  = (const float*)d_in[11];
    const float* bn1g = (const float*)d_in[12];
    const float* bn1b = (const float*)d_in[13];
    const float* c2w  = (const float*)d_in[14];
    const float* bn2g = (const float*)d_in[15];
    const float* bn2b = (const float*)d_in[16];
    const float* scw  = (const float*)d_in[17];
    const float* bnscg= (const float*)d_in[18];
    const float* bnscb= (const float*)d_in[19];
    float* out = (float*)d_out;

    float *xm, *y1, *ysc, *y2, *Ssc, *Qsc, *S2, *Q2;
    uint *wsu, *w2u;
    cudaGetSymbolAddress((void**)&xm,  g_xm);
    cudaGetSymbolAddress((void**)&y1,  g_y1);
    cudaGetSymbolAddress((void**)&ysc, g_ysc);
    cudaGetSymbolAddress((void**)&y2,  g_y2);
    cudaGetSymbolAddress((void**)&Ssc, g_ssc);
    cudaGetSymbolAddress((void**)&Qsc, g_qsc);
    cudaGetSymbolAddress((void**)&S2,  g_s2);
    cudaGetSymbolAddress((void**)&Q2,  g_q2);
    cudaGetSymbolAddress((void**)&wsu, g_wsu);
    cudaGetSymbolAddress((void**)&w2u, g_w2u);

    static int smem_set = 0;
    if (!smem_set){
        cudaFuncSetAttribute(k_conv3, cudaFuncAttributeMaxDynamicSharedMemorySize, C3_SMEM);
        smem_set = 1;
    }

    k_init<<<576, 256>>>(c1w, c2w, scw);
    k_dce1<<<dim3(8,16), 128>>>(dce, Wd1);
    k_dce2<<<16, 128>>>(bd1, Wd2, bd2);
    k_spatial<<<dim3(128,16), 256>>>(x, dwc);
    k_mod<<<16, 128>>>(Wsh, bsh, Wex, bex);
    k_premul<<<4096, 256>>>(x);
    k_conv3<<<dim3(128,16), 256, C3_SMEM>>>();
    k_gemm<<<dim3(128,16), 256>>>(xm, wsu, ysc, Ssc, Qsc);
    k_coefA<<<1, 128>>>(bn1g, bn1b, bnscg, bnscb);
    k_prep2<<<4096, 256>>>();
    k_gemm<<<dim3(128,16), 256>>>(xm, w2u, y2, S2, Q2);
    k_coefB<<<1, 128>>>(bn2g, bn2b);
    k_final<<<4096, 256>>>(out);
}